// round 3
// baseline (speedup 1.0000x reference)
#include <cuda_runtime.h>
#include <math.h>

// Problem constants
#define BB   32
#define SS   1024
#define DD   3
#define NF   512
#define NS   64
#define HID  100
#define FSZ  256

// Decomposition
#define NSC  8            // S chunks
#define SCH  (SS/NSC)     // 128 steps per chunk
#define NFC  4            // nf chunks
#define FCH  (NF/NFC)     // 128 nf per block (= threads)

// Scratch (device globals: allocation-free per harness rules)
__device__ float g_H[NF*HID];
__device__ float g_F[NF*FSZ];
__device__ float g_Womg[NF*3];
__device__ float g_totC[BB*NSC*NF];
__device__ float g_totS[BB*NSC*NF];
__device__ float g_part[(size_t)BB*SS*16];

// ---------------- Fourier-feature MLP (tiny) ----------------

__global__ void k_hidden(const float* __restrict__ noise,
                         const float* __restrict__ W1,
                         const float* __restrict__ b1) {
    int idx = blockIdx.x*blockDim.x + threadIdx.x;
    if (idx >= NF*HID) return;
    int f = idx / HID, j = idx % HID;
    float acc = b1[j];
    const float* nrow = noise + f*NS;
    #pragma unroll 8
    for (int k = 0; k < NS; k++) acc = fmaf(nrow[k], W1[k*HID + j], acc);
    g_H[idx] = tanhf(acc);
}

__global__ void k_fourier(const float* __restrict__ W2,
                          const float* __restrict__ b2) {
    int idx = blockIdx.x*blockDim.x + threadIdx.x;
    if (idx >= NF*FSZ) return;
    int f = idx / FSZ, i = idx % FSZ;
    float acc = b2[i];
    const float* h = g_H + f*HID;
    #pragma unroll 4
    for (int j = 0; j < HID; j++) acc = fmaf(h[j], W2[j*FSZ + i], acc);
    g_F[idx] = tanhf(acc);
}

__global__ void k_womg(const float* __restrict__ W) {
    int n = blockIdx.x*blockDim.x + threadIdx.x;
    if (n >= NF) return;
    float w0 = 0.f, w1 = 0.f, w2 = 0.f;
    const float* frow = g_F + n*FSZ;
    #pragma unroll 4
    for (int i = 0; i < FSZ; i++) {
        float fv = frow[i];
        w0 = fmaf(fv, W[i*3+0], w0);
        w1 = fmaf(fv, W[i*3+1], w1);
        w2 = fmaf(fv, W[i*3+2], w2);
    }
    g_Womg[n*3+0] = w0;
    g_Womg[n*3+1] = w1;
    g_Womg[n*3+2] = w2;
}

// ---------------- Pass A: per-S-chunk trig totals ----------------

__global__ void __launch_bounds__(FCH) k_passA(const float* __restrict__ X) {
    int t  = threadIdx.x;
    int fc = blockIdx.x, sc = blockIdx.y, b = blockIdx.z;
    int n  = fc*FCH + t;
    float w0 = g_Womg[n*3+0], w1 = g_Womg[n*3+1], w2 = g_Womg[n*3+2];

    __shared__ float sx[SCH*3];
    int s0 = sc*SCH;
    const float* xp = X + ((size_t)b*SS + s0)*3;
    for (int i = t; i < SCH*3; i += FCH) sx[i] = xp[i];
    __syncthreads();

    float sumC = 0.f, sumS = 0.f;
    #pragma unroll 4
    for (int k = 0; k < SCH; k++) {
        float th = fmaf(sx[k*3+2], w2, fmaf(sx[k*3+1], w1, sx[k*3]*w0));
        float sv, cv;
        sincosf(th, &sv, &cv);
        sumC += cv; sumS += sv;
    }
    g_totC[(b*NSC + sc)*NF + n] = sumC;
    g_totS[(b*NSC + sc)*NF + n] = sumS;
}

// ---------------- Pass C: contributions with scan offsets ----------------

__global__ void __launch_bounds__(FCH) k_passC(const float* __restrict__ X) {
    int t  = threadIdx.x;
    int fc = blockIdx.x, sc = blockIdx.y, b = blockIdx.z;
    int n  = fc*FCH + t;
    float w0 = g_Womg[n*3+0], w1 = g_Womg[n*3+1], w2 = g_Womg[n*3+2];

    // exclusive offsets from preceding S chunks
    float runC = 0.f, runS = 0.f;
    for (int p = 0; p < sc; p++) {
        runC += g_totC[(b*NSC + p)*NF + n];
        runS += g_totS[(b*NSC + p)*NF + n];
    }

    __shared__ float sx[SCH*3];
    int s0 = sc*SCH;
    const float* xp = X + ((size_t)b*SS + s0)*3;
    for (int i = t; i < SCH*3; i += FCH) sx[i] = xp[i];
    __syncthreads();

    int lane = t & 31, warp = t >> 5;
    int slot = fc*4 + warp;

    for (int k = 0; k < SCH; k++) {
        float th = fmaf(sx[k*3+2], w2, fmaf(sx[k*3+1], w1, sx[k*3]*w0));
        float sv, cv;
        sincosf(th, &sv, &cv);
        float contrib = cv*runC + sv*runS;   // uses EXCLUSIVE prefix
        runC += cv; runS += sv;
        #pragma unroll
        for (int o = 16; o; o >>= 1)
            contrib += __shfl_xor_sync(0xffffffffu, contrib, o);
        if (lane == 0)
            g_part[((size_t)(b*SS + s0 + k))*16 + slot] = contrib;
    }
}

// ---------------- Final: lam + loglik ----------------

__global__ void k_final(const float* __restrict__ X,
                        const float* __restrict__ alpha,
                        float* __restrict__ out) {
    int idx = blockIdx.x*blockDim.x + threadIdx.x;
    if (idx >= BB*SS) return;
    const float* p = g_part + (size_t)idx*16;
    float s = 0.f;
    #pragma unroll
    for (int i = 0; i < 16; i++) s += p[i];
    float lam = fmaf(alpha[0], s * (1.0f/NF), 10.0f);
    out[idx] = lam;

    int b = idx / SS, si = idx % SS;
    float x0 = X[(size_t)idx*3];
    float mask = (x0 > 0.f) ? 1.f : 0.f;
    const float C2 = -3947.8417604357433f;   // -MU*T*(2*pi)^(D-1)
    out[BB*SS + b*(SS+1) + si] = logf(lam)*mask + C2;
    if (idx < BB)                             // extra (S+1)-th column
        out[BB*SS + idx*(SS+1) + SS] = C2;
}

// ---------------- Launch ----------------

extern "C" void kernel_launch(void* const* d_in, const int* in_sizes, int n_in,
                              void* d_out, int out_size) {
    const float* X     = (const float*)d_in[0];
    const float* noise = (const float*)d_in[1];
    const float* W1    = (const float*)d_in[2];
    const float* b1    = (const float*)d_in[3];
    const float* W2    = (const float*)d_in[4];
    const float* b2    = (const float*)d_in[5];
    const float* W     = (const float*)d_in[6];
    const float* alpha = (const float*)d_in[7];
    float* out = (float*)d_out;

    k_hidden <<<(NF*HID + 255)/256, 256>>>(noise, W1, b1);
    k_fourier<<<(NF*FSZ + 255)/256, 256>>>(W2, b2);
    k_womg   <<<(NF + 255)/256, 256>>>(W);

    dim3 grid(NFC, NSC, BB);
    k_passA<<<grid, FCH>>>(X);
    k_passC<<<grid, FCH>>>(X);

    k_final<<<(BB*SS + 255)/256, 256>>>(X, alpha, out);
}

// round 5
// speedup vs baseline: 1.3744x; 1.3744x over previous
#include <cuda_runtime.h>
#include <math.h>

// Problem constants
#define BB   32
#define SS   1024
#define DD   3
#define NF   512
#define NS   64
#define HID  100
#define FSZ  256

// Decomposition
#define NSC  8            // S chunks
#define SCH  (SS/NSC)     // 128 steps per chunk
#define NFC  4            // nf chunks
#define FCH  (NF/NFC)     // 128 nf per block (= threads)

// Scratch (device globals: allocation-free per harness rules)
__device__ float g_H[NF*HID];
__device__ float g_F[NF*FSZ];
__device__ float g_Womg[NF*3];
__device__ float g_totC[BB*NSC*NF];
__device__ float g_totS[BB*NSC*NF];
__device__ float g_part[(size_t)BB*SS*16];

// Warp-wide float add reduction (SHFL butterfly; redux.f32 not available
// via compute_103 PTX target).
__device__ __forceinline__ float warp_sum(float v) {
    #pragma unroll
    for (int o = 16; o; o >>= 1) v += __shfl_xor_sync(0xffffffffu, v, o);
    return v;
}

// ---------------- Fourier-feature MLP (tiny) ----------------

__global__ void k_hidden(const float* __restrict__ noise,
                         const float* __restrict__ W1,
                         const float* __restrict__ b1) {
    int idx = blockIdx.x*blockDim.x + threadIdx.x;
    if (idx >= NF*HID) return;
    int f = idx / HID, j = idx % HID;
    float acc = b1[j];
    const float* nrow = noise + f*NS;
    #pragma unroll 8
    for (int k = 0; k < NS; k++) acc = fmaf(nrow[k], W1[k*HID + j], acc);
    g_H[idx] = tanhf(acc);
}

__global__ void k_fourier(const float* __restrict__ W2,
                          const float* __restrict__ b2) {
    int idx = blockIdx.x*blockDim.x + threadIdx.x;
    if (idx >= NF*FSZ) return;
    int f = idx / FSZ, i = idx % FSZ;
    float acc = b2[i];
    const float* h = g_H + f*HID;
    #pragma unroll 4
    for (int j = 0; j < HID; j++) acc = fmaf(h[j], W2[j*FSZ + i], acc);
    g_F[idx] = tanhf(acc);
}

__global__ void k_womg(const float* __restrict__ W) {
    int n = blockIdx.x*blockDim.x + threadIdx.x;
    if (n >= NF) return;
    float w0 = 0.f, w1 = 0.f, w2 = 0.f;
    const float* frow = g_F + n*FSZ;
    #pragma unroll 4
    for (int i = 0; i < FSZ; i++) {
        float fv = frow[i];
        w0 = fmaf(fv, W[i*3+0], w0);
        w1 = fmaf(fv, W[i*3+1], w1);
        w2 = fmaf(fv, W[i*3+2], w2);
    }
    g_Womg[n*3+0] = w0;
    g_Womg[n*3+1] = w1;
    g_Womg[n*3+2] = w2;
}

// ---------------- Pass A: per-S-chunk trig totals ----------------

__global__ void __launch_bounds__(FCH) k_passA(const float* __restrict__ X) {
    int t  = threadIdx.x;
    int fc = blockIdx.x, sc = blockIdx.y, b = blockIdx.z;
    int n  = fc*FCH + t;
    float w0 = g_Womg[n*3+0], w1 = g_Womg[n*3+1], w2 = g_Womg[n*3+2];

    __shared__ float sx[SCH*3];
    int s0 = sc*SCH;
    const float* xp = X + ((size_t)b*SS + s0)*3;
    for (int i = t; i < SCH*3; i += FCH) sx[i] = xp[i];
    __syncthreads();

    float sumC = 0.f, sumS = 0.f;
    #pragma unroll 8
    for (int k = 0; k < SCH; k++) {
        float th = fmaf(sx[k*3+2], w2, fmaf(sx[k*3+1], w1, sx[k*3]*w0));
        float sv, cv;
        __sincosf(th, &sv, &cv);
        sumC += cv; sumS += sv;
    }
    g_totC[(b*NSC + sc)*NF + n] = sumC;
    g_totS[(b*NSC + sc)*NF + n] = sumS;
}

// ---------------- Pass C: contributions with scan offsets ----------------

__global__ void __launch_bounds__(FCH) k_passC(const float* __restrict__ X) {
    int t  = threadIdx.x;
    int fc = blockIdx.x, sc = blockIdx.y, b = blockIdx.z;
    int n  = fc*FCH + t;
    float w0 = g_Womg[n*3+0], w1 = g_Womg[n*3+1], w2 = g_Womg[n*3+2];

    // exclusive offsets from preceding S chunks
    float runC = 0.f, runS = 0.f;
    for (int p = 0; p < sc; p++) {
        runC += g_totC[(b*NSC + p)*NF + n];
        runS += g_totS[(b*NSC + p)*NF + n];
    }

    __shared__ float sx[SCH*3];
    int s0 = sc*SCH;
    const float* xp = X + ((size_t)b*SS + s0)*3;
    for (int i = t; i < SCH*3; i += FCH) sx[i] = xp[i];
    __syncthreads();

    int lane = t & 31, warp = t >> 5;
    int slot = fc*4 + warp;
    float* pout = g_part + ((size_t)(b*SS + s0))*16 + slot;

    #pragma unroll 4
    for (int k = 0; k < SCH; k++) {
        float th = fmaf(sx[k*3+2], w2, fmaf(sx[k*3+1], w1, sx[k*3]*w0));
        float sv, cv;
        __sincosf(th, &sv, &cv);
        float contrib = cv*runC + sv*runS;   // uses EXCLUSIVE prefix
        runC += cv; runS += sv;
        contrib = warp_sum(contrib);
        if (lane == 0)
            pout[(size_t)k*16] = contrib;
    }
}

// ---------------- Final: lam + loglik ----------------

__global__ void k_final(const float* __restrict__ X,
                        const float* __restrict__ alpha,
                        float* __restrict__ out) {
    int idx = blockIdx.x*blockDim.x + threadIdx.x;
    if (idx >= BB*SS) return;
    const float* p = g_part + (size_t)idx*16;
    float s = 0.f;
    #pragma unroll
    for (int i = 0; i < 16; i++) s += p[i];
    float lam = fmaf(alpha[0], s * (1.0f/NF), 10.0f);
    out[idx] = lam;

    int b = idx / SS, si = idx % SS;
    float x0 = X[(size_t)idx*3];
    float mask = (x0 > 0.f) ? 1.f : 0.f;
    const float C2 = -3947.8417604357433f;   // -MU*T*(2*pi)^(D-1)
    out[BB*SS + b*(SS+1) + si] = logf(lam)*mask + C2;
    if (idx < BB)                             // extra (S+1)-th column
        out[BB*SS + idx*(SS+1) + SS] = C2;
}

// ---------------- Launch ----------------

extern "C" void kernel_launch(void* const* d_in, const int* in_sizes, int n_in,
                              void* d_out, int out_size) {
    const float* X     = (const float*)d_in[0];
    const float* noise = (const float*)d_in[1];
    const float* W1    = (const float*)d_in[2];
    const float* b1    = (const float*)d_in[3];
    const float* W2    = (const float*)d_in[4];
    const float* b2    = (const float*)d_in[5];
    const float* W     = (const float*)d_in[6];
    const float* alpha = (const float*)d_in[7];
    float* out = (float*)d_out;

    k_hidden <<<(NF*HID + 255)/256, 256>>>(noise, W1, b1);
    k_fourier<<<(NF*FSZ + 255)/256, 256>>>(W2, b2);
    k_womg   <<<(NF + 255)/256, 256>>>(W);

    dim3 grid(NFC, NSC, BB);
    k_passA<<<grid, FCH>>>(X);
    k_passC<<<grid, FCH>>>(X);

    k_final<<<(BB*SS + 255)/256, 256>>>(X, alpha, out);
}

// round 6
// speedup vs baseline: 2.7397x; 1.9934x over previous
#include <cuda_runtime.h>
#include <math.h>

// Problem constants
#define BB   32
#define SS   1024
#define DD   3
#define NF   512
#define NS   64
#define HID  100
#define FSZ  256

// Decomposition
#define NSC  16           // S chunks
#define SCH  (SS/NSC)     // 64 steps per chunk
#define NFC  4            // nf chunks
#define FCH  (NF/NFC)     // 128 nf per block (= threads)

// Scratch (device globals: allocation-free per harness rules)
__device__ float g_Womg[NF*3];
__device__ float g_totC[BB*NSC*NF];
__device__ float g_totS[BB*NSC*NF];
__device__ float g_part[(size_t)BB*SS*16];

// Warp-wide float add reduction (SHFL butterfly; redux.f32 not available
// via compute_103 PTX target).
__device__ __forceinline__ float warp_sum(float v) {
    #pragma unroll
    for (int o = 16; o; o >>= 1) v += __shfl_xor_sync(0xffffffffu, v, o);
    return v;
}

// ---------------- Fused Fourier-feature MLP ----------------
// One block per fourier sample f. hidden(100) -> fourier(256) -> Womg(3),
// all staged through shared memory. 512 blocks x 128 threads.

__global__ void __launch_bounds__(128) k_mlp(const float* __restrict__ noise,
                                             const float* __restrict__ W1,
                                             const float* __restrict__ b1,
                                             const float* __restrict__ W2,
                                             const float* __restrict__ b2,
                                             const float* __restrict__ W) {
    int f = blockIdx.x;
    int t = threadIdx.x;

    __shared__ float s_noise[NS];
    __shared__ float s_h[HID];
    __shared__ float s_fs[FSZ];
    __shared__ float s_red[4][3];

    if (t < NS) s_noise[t] = noise[f*NS + t];
    __syncthreads();

    // hidden: h[j] = tanh(b1[j] + sum_k noise[k] * W1[k,j])
    if (t < HID) {
        float acc = b1[t];
        #pragma unroll 8
        for (int k = 0; k < NS; k++)
            acc = fmaf(s_noise[k], W1[k*HID + t], acc);
        s_h[t] = tanhf(acc);
    }
    __syncthreads();

    // fourier: fs[i] = tanh(b2[i] + sum_j h[j] * W2[j,i]); 2 i's per thread
    float fs0, fs1;
    {
        int i0 = t, i1 = t + 128;
        float a0 = b2[i0], a1 = b2[i1];
        #pragma unroll 4
        for (int j = 0; j < HID; j++) {
            float h = s_h[j];
            a0 = fmaf(h, W2[j*FSZ + i0], a0);
            a1 = fmaf(h, W2[j*FSZ + i1], a1);
        }
        fs0 = tanhf(a0); fs1 = tanhf(a1);
        s_fs[i0] = fs0; s_fs[i1] = fs1;
    }

    // Womg[f][d] = sum_i fs[i] * W[i,d]
    int i0 = t, i1 = t + 128;
    float p0 = fmaf(fs0, W[i0*3+0], fs1*W[i1*3+0]);
    float p1 = fmaf(fs0, W[i0*3+1], fs1*W[i1*3+1]);
    float p2 = fmaf(fs0, W[i0*3+2], fs1*W[i1*3+2]);
    p0 = warp_sum(p0); p1 = warp_sum(p1); p2 = warp_sum(p2);
    int lane = t & 31, warp = t >> 5;
    if (lane == 0) { s_red[warp][0] = p0; s_red[warp][1] = p1; s_red[warp][2] = p2; }
    __syncthreads();
    if (t < 3) {
        float v = s_red[0][t] + s_red[1][t] + s_red[2][t] + s_red[3][t];
        g_Womg[f*3 + t] = v;
    }
}

// ---------------- Pass A: per-S-chunk trig totals ----------------

__global__ void __launch_bounds__(FCH) k_passA(const float* __restrict__ X) {
    int t  = threadIdx.x;
    int fc = blockIdx.x, sc = blockIdx.y, b = blockIdx.z;
    int n  = fc*FCH + t;
    float w0 = g_Womg[n*3+0], w1 = g_Womg[n*3+1], w2 = g_Womg[n*3+2];

    __shared__ float sx[SCH*3];
    int s0 = sc*SCH;
    const float* xp = X + ((size_t)b*SS + s0)*3;
    for (int i = t; i < SCH*3; i += FCH) sx[i] = xp[i];
    __syncthreads();

    float sumC = 0.f, sumS = 0.f;
    #pragma unroll 8
    for (int k = 0; k < SCH; k++) {
        float th = fmaf(sx[k*3+2], w2, fmaf(sx[k*3+1], w1, sx[k*3]*w0));
        float sv, cv;
        __sincosf(th, &sv, &cv);
        sumC += cv; sumS += sv;
    }
    g_totC[(b*NSC + sc)*NF + n] = sumC;
    g_totS[(b*NSC + sc)*NF + n] = sumS;
}

// ---------------- Pass C: contributions with scan offsets ----------------

__global__ void __launch_bounds__(FCH) k_passC(const float* __restrict__ X) {
    int t  = threadIdx.x;
    int fc = blockIdx.x, sc = blockIdx.y, b = blockIdx.z;
    int n  = fc*FCH + t;
    float w0 = g_Womg[n*3+0], w1 = g_Womg[n*3+1], w2 = g_Womg[n*3+2];

    // exclusive offsets from preceding S chunks
    float runC = 0.f, runS = 0.f;
    for (int p = 0; p < sc; p++) {
        runC += g_totC[(b*NSC + p)*NF + n];
        runS += g_totS[(b*NSC + p)*NF + n];
    }

    __shared__ float sx[SCH*3];
    int s0 = sc*SCH;
    const float* xp = X + ((size_t)b*SS + s0)*3;
    for (int i = t; i < SCH*3; i += FCH) sx[i] = xp[i];
    __syncthreads();

    int lane = t & 31, warp = t >> 5;
    int slot = fc*4 + warp;
    float* pout = g_part + ((size_t)(b*SS + s0))*16 + slot;

    #pragma unroll 4
    for (int k = 0; k < SCH; k++) {
        float th = fmaf(sx[k*3+2], w2, fmaf(sx[k*3+1], w1, sx[k*3]*w0));
        float sv, cv;
        __sincosf(th, &sv, &cv);
        float contrib = cv*runC + sv*runS;   // uses EXCLUSIVE prefix
        runC += cv; runS += sv;
        contrib = warp_sum(contrib);
        if (lane == 0)
            pout[(size_t)k*16] = contrib;
    }
}

// ---------------- Final: lam + loglik ----------------

__global__ void k_final(const float* __restrict__ X,
                        const float* __restrict__ alpha,
                        float* __restrict__ out) {
    int idx = blockIdx.x*blockDim.x + threadIdx.x;
    if (idx >= BB*SS) return;
    const float* p = g_part + (size_t)idx*16;
    float s = 0.f;
    #pragma unroll
    for (int i = 0; i < 16; i++) s += p[i];
    float lam = fmaf(alpha[0], s * (1.0f/NF), 10.0f);
    out[idx] = lam;

    int b = idx / SS, si = idx % SS;
    float x0 = X[(size_t)idx*3];
    float mask = (x0 > 0.f) ? 1.f : 0.f;
    const float C2 = -3947.8417604357433f;   // -MU*T*(2*pi)^(D-1)
    out[BB*SS + b*(SS+1) + si] = logf(lam)*mask + C2;
    if (idx < BB)                             // extra (S+1)-th column
        out[BB*SS + idx*(SS+1) + SS] = C2;
}

// ---------------- Launch ----------------

extern "C" void kernel_launch(void* const* d_in, const int* in_sizes, int n_in,
                              void* d_out, int out_size) {
    const float* X     = (const float*)d_in[0];
    const float* noise = (const float*)d_in[1];
    const float* W1    = (const float*)d_in[2];
    const float* b1    = (const float*)d_in[3];
    const float* W2    = (const float*)d_in[4];
    const float* b2    = (const float*)d_in[5];
    const float* W     = (const float*)d_in[6];
    const float* alpha = (const float*)d_in[7];
    float* out = (float*)d_out;

    k_mlp<<<NF, 128>>>(noise, W1, b1, W2, b2, W);

    dim3 grid(NFC, NSC, BB);
    k_passA<<<grid, FCH>>>(X);
    k_passC<<<grid, FCH>>>(X);

    k_final<<<(BB*SS + 255)/256, 256>>>(X, alpha, out);
}